// round 9
// baseline (speedup 1.0000x reference)
#include <cuda_runtime.h>
#include <cuda_fp16.h>
#include <cstdint>

// Problem constants (from reference setup_inputs)
#define MAXN 50000
#define MAXE 800000
#define NGRAPH 512

// Scratch (device globals: allocation-free).
__device__ __align__(128) __half g_Pmain[(size_t)MAXN * 64];  // [n][o*8+k]
__device__ __align__(128) __half g_Pbias[(size_t)MAXN * 8];
__device__ __align__(128) float g_agg1[(size_t)MAXN * 8];
__device__ __align__(128) float g_agg2[(size_t)MAXN * 8];
// CSR-by-dst (built once per launch, reused by both layers)
__device__ __align__(128) int  g_cnt[MAXN];
__device__ __align__(128) int  g_off[MAXN + 1];
__device__ __align__(128) int  g_cur[MAXN];
__device__ __align__(128) int2 g_bin[MAXE];      // {src, eid}

// -----------------------------------------------------------------------------
// CSR build
// -----------------------------------------------------------------------------
__global__ void zero_cnt_kernel(int* __restrict__ cnt, int N)
{
    int i = blockIdx.x * blockDim.x + threadIdx.x;
    if (i < N) cnt[i] = 0;
}

__global__ void count_kernel(const int* __restrict__ ei, int* __restrict__ cnt, int E)
{
    int e = blockIdx.x * blockDim.x + threadIdx.x;
    if (e < E) atomicAdd(cnt + __ldg(ei + E + e), 1);
}

// Single-block scan: 1024 threads, each owns a contiguous chunk.
__global__ void scan_kernel(const int* __restrict__ cnt,
                            int* __restrict__ off, int* __restrict__ cur, int N)
{
    __shared__ int sums[1024];
    int t = threadIdx.x;
    int C = (N + 1023) / 1024;
    int lo = t * C;
    int hi = min(lo + C, N);
    int s = 0;
    for (int i = lo; i < hi; i++) s += cnt[i];
    sums[t] = s;
    __syncthreads();
    for (int d = 1; d < 1024; d <<= 1) {
        int v = (t >= d) ? sums[t - d] : 0;
        __syncthreads();
        sums[t] += v;
        __syncthreads();
    }
    int base = (t == 0) ? 0 : sums[t - 1];
    for (int i = lo; i < hi; i++) {
        off[i] = base;
        cur[i] = base;
        base += cnt[i];
    }
    if (t == 1023) off[N] = sums[1023];
}

__global__ void fill_kernel(const int* __restrict__ ei,
                            int* __restrict__ cur, int2* __restrict__ bin, int E)
{
    int e = blockIdx.x * blockDim.x + threadIdx.x;
    if (e >= E) return;
    int dst = __ldg(ei + E + e);
    int src = __ldg(ei + e);
    int pos = atomicAdd(cur + dst, 1);
    bin[pos] = make_int2(src, e);
}

// -----------------------------------------------------------------------------
// Node precompute: Pmain[n,o,k] = sum_i in[n,i] * We[k, i*8+o]   (fp16, transposed)
//                  Pbias[n,o]   = sum_i in[n,i] * be[i*8+o]
//                  agg[n,o] = b[o] + sum_i in[n,i] * root[i,o]   (fp32 root init)
// -----------------------------------------------------------------------------
template<int IN, bool RELU>
__global__ void node_prep_kernel(
    const float* __restrict__ xin,
    const float* __restrict__ We,    // [8, IN*8]
    const float* __restrict__ be,    // [IN*8]
    const float* __restrict__ root,  // [IN, 8]
    const float* __restrict__ bvec,  // [8]
    __half* __restrict__ Pmain,      // [N, 64]
    __half* __restrict__ Pbias,      // [N, 8]
    float* __restrict__ agg,         // [N, 8]
    int N)
{
    __shared__ float sW[8 * IN * 8];
    __shared__ float sB[IN * 8];
    __shared__ float sR[IN * 8];
    __shared__ float sb[8];
    for (int i = threadIdx.x; i < 8 * IN * 8; i += blockDim.x) sW[i] = We[i];
    for (int i = threadIdx.x; i < IN * 8; i += blockDim.x) { sB[i] = be[i]; sR[i] = root[i]; }
    if (threadIdx.x < 8) sb[threadIdx.x] = bvec[threadIdx.x];
    __syncthreads();

    int idx = blockIdx.x * blockDim.x + threadIdx.x;
    int n = idx >> 3;
    int o = idx & 7;
    if (n >= N) return;

    float xv[IN];
#pragma unroll
    for (int i = 0; i < IN; i++) {
        float v = __ldg(xin + (size_t)n * IN + i);
        xv[i] = RELU ? fmaxf(v, 0.0f) : v;
    }

    __half2 packed[4];
#pragma unroll
    for (int kk = 0; kk < 4; kk++) {
        float a0 = 0.0f, a1 = 0.0f;
#pragma unroll
        for (int i = 0; i < IN; i++) {
            a0 = fmaf(xv[i], sW[(2 * kk)     * IN * 8 + i * 8 + o], a0);
            a1 = fmaf(xv[i], sW[(2 * kk + 1) * IN * 8 + i * 8 + o], a1);
        }
        packed[kk] = __floats2half2_rn(a0, a1);
    }
    *reinterpret_cast<uint4*>(Pmain + (size_t)n * 64 + o * 8) =
        *reinterpret_cast<uint4*>(packed);

    float accb = 0.0f;
#pragma unroll
    for (int i = 0; i < IN; i++) accb = fmaf(xv[i], sB[i * 8 + o], accb);
    Pbias[(size_t)n * 8 + o] = __float2half_rn(accb);

    float accr = sb[o];
#pragma unroll
    for (int i = 0; i < IN; i++) accr = fmaf(xv[i], sR[i * 8 + o], accr);
    agg[(size_t)n * 8 + o] = accr;
}

// -----------------------------------------------------------------------------
// Edge phase, owner-computes over CSR bins (NO atomics):
//   8-lane group owns dst node g; iterates its bin range, accumulating
//   msg[o] = Pbias[src,o] + sum_k ea[e,k] * Pmain[src,o,k] into a register.
//   One plain STG per (node, o) at the end.
// -----------------------------------------------------------------------------
__global__ void edge_csr_kernel(
    const float*  __restrict__ ea,     // [E, 8]
    const __half* __restrict__ Pmain,  // [N, 64]
    const __half* __restrict__ Pbias,  // [N, 8]
    const int*    __restrict__ off,    // [N+1]
    const int2*   __restrict__ bin,    // [E] {src, eid}
    float*        __restrict__ agg,    // [N, 8] (pre-initialized with root+b)
    int N)
{
    int t = blockIdx.x * blockDim.x + threadIdx.x;
    int g = t >> 3;
    int o = t & 7;
    if (g >= N) return;

    int j   = __ldg(off + g);
    int end = __ldg(off + g + 1);
    float acc = agg[(size_t)g * 8 + o];

    for (; j + 1 < end; j += 2) {
        int2 se0 = __ldg(bin + j);
        int2 se1 = __ldg(bin + j + 1);

        const float4* eap0 = reinterpret_cast<const float4*>(ea + (size_t)se0.y * 8);
        const float4* eap1 = reinterpret_cast<const float4*>(ea + (size_t)se1.y * 8);
        float4 a00 = __ldg(eap0);
        float4 a01 = __ldg(eap0 + 1);
        float4 a10 = __ldg(eap1);
        float4 a11 = __ldg(eap1 + 1);

        uint4 raw0 = __ldg(reinterpret_cast<const uint4*>(Pmain + (size_t)se0.x * 64 + o * 8));
        uint4 raw1 = __ldg(reinterpret_cast<const uint4*>(Pmain + (size_t)se1.x * 64 + o * 8));
        float b0 = __half2float(__ldg(Pbias + (size_t)se0.x * 8 + o));
        float b1 = __half2float(__ldg(Pbias + (size_t)se1.x * 8 + o));

        __half2 ph0[4], ph1[4];
        *reinterpret_cast<uint4*>(ph0) = raw0;
        *reinterpret_cast<uint4*>(ph1) = raw1;

        float m0 = b0;
        float2 q;
        q = __half22float2(ph0[0]); m0 = fmaf(a00.x, q.x, m0); m0 = fmaf(a00.y, q.y, m0);
        q = __half22float2(ph0[1]); m0 = fmaf(a00.z, q.x, m0); m0 = fmaf(a00.w, q.y, m0);
        q = __half22float2(ph0[2]); m0 = fmaf(a01.x, q.x, m0); m0 = fmaf(a01.y, q.y, m0);
        q = __half22float2(ph0[3]); m0 = fmaf(a01.z, q.x, m0); m0 = fmaf(a01.w, q.y, m0);

        float m1 = b1;
        q = __half22float2(ph1[0]); m1 = fmaf(a10.x, q.x, m1); m1 = fmaf(a10.y, q.y, m1);
        q = __half22float2(ph1[1]); m1 = fmaf(a10.z, q.x, m1); m1 = fmaf(a10.w, q.y, m1);
        q = __half22float2(ph1[2]); m1 = fmaf(a11.x, q.x, m1); m1 = fmaf(a11.y, q.y, m1);
        q = __half22float2(ph1[3]); m1 = fmaf(a11.z, q.x, m1); m1 = fmaf(a11.w, q.y, m1);

        acc += m0 + m1;
    }
    if (j < end) {
        int2 se = __ldg(bin + j);
        const float4* eap = reinterpret_cast<const float4*>(ea + (size_t)se.y * 8);
        float4 a0 = __ldg(eap);
        float4 a1 = __ldg(eap + 1);
        uint4 raw = __ldg(reinterpret_cast<const uint4*>(Pmain + (size_t)se.x * 64 + o * 8));
        float m = __half2float(__ldg(Pbias + (size_t)se.x * 8 + o));
        __half2 ph[4];
        *reinterpret_cast<uint4*>(ph) = raw;
        float2 q;
        q = __half22float2(ph[0]); m = fmaf(a0.x, q.x, m); m = fmaf(a0.y, q.y, m);
        q = __half22float2(ph[1]); m = fmaf(a0.z, q.x, m); m = fmaf(a0.w, q.y, m);
        q = __half22float2(ph[2]); m = fmaf(a1.x, q.x, m); m = fmaf(a1.y, q.y, m);
        q = __half22float2(ph[3]); m = fmaf(a1.z, q.x, m); m = fmaf(a1.w, q.y, m);
        acc += m;
    }

    agg[(size_t)g * 8 + o] = acc;   // coalesced 32B per group, no atomics
}

// -----------------------------------------------------------------------------
// Output init: out[g] = blast[0]
// -----------------------------------------------------------------------------
__global__ void init_out_kernel(float* __restrict__ out, const float* __restrict__ blast, int G)
{
    int i = blockIdx.x * blockDim.x + threadIdx.x;
    if (i < G) out[i] = __ldg(blast);
}

// -----------------------------------------------------------------------------
// Pool + readout: out[batch[n]] += relu(agg2[n]) . Wlast
// batch is sorted -> warp-segmented reduction before atomics.
// -----------------------------------------------------------------------------
__global__ void pool_kernel(
    const float* __restrict__ agg2,
    const int*   __restrict__ batch,
    const float* __restrict__ Wlast,  // [8]
    float*       __restrict__ out,    // [G]
    int N)
{
    int n = blockIdx.x * blockDim.x + threadIdx.x;
    int lane = threadIdx.x & 31;
    bool valid = (n < N);
    float s = 0.0f;
    int g = -1;
    if (valid) {
        g = __ldg(batch + n);
#pragma unroll
        for (int o = 0; o < 8; o++) {
            float h = fmaxf(__ldg(agg2 + (size_t)n * 8 + o), 0.0f);
            s = fmaf(h, __ldg(Wlast + o), s);
        }
    }
#pragma unroll
    for (int d = 1; d < 32; d <<= 1) {
        float v = __shfl_down_sync(0xffffffffu, s, d);
        int gg   = __shfl_down_sync(0xffffffffu, g, d);
        if (lane + d < 32 && gg == g) s += v;
    }
    int gprev = __shfl_up_sync(0xffffffffu, g, 1);
    bool head = (lane == 0) || (gprev != g);
    if (valid && head) atomicAdd(out + g, s);
}

// -----------------------------------------------------------------------------
// Launch
// Inputs (metadata order): x, edge_index, edge_attr, batch,
//   We1, be1, root1, b1, We2, be2, root2, b2, Wlast, blast
// -----------------------------------------------------------------------------
extern "C" void kernel_launch(void* const* d_in, const int* in_sizes, int n_in,
                              void* d_out, int out_size)
{
    const float* x     = (const float*)d_in[0];
    const int*   ei    = (const int*)  d_in[1];
    const float* ea    = (const float*)d_in[2];
    const int*   batch = (const int*)  d_in[3];
    const float* We1   = (const float*)d_in[4];
    const float* be1   = (const float*)d_in[5];
    const float* root1 = (const float*)d_in[6];
    const float* b1    = (const float*)d_in[7];
    const float* We2   = (const float*)d_in[8];
    const float* be2   = (const float*)d_in[9];
    const float* root2 = (const float*)d_in[10];
    const float* b2    = (const float*)d_in[11];
    const float* Wlast = (const float*)d_in[12];
    const float* blast = (const float*)d_in[13];
    float* out = (float*)d_out;

    const int N = in_sizes[0] / 16;   // 50000
    const int E = in_sizes[1] / 2;    // 800000
    const int G = out_size;           // 512

    __half *pPm = nullptr, *pPb = nullptr;
    float *pA1 = nullptr, *pA2 = nullptr;
    int *pCnt = nullptr, *pOff = nullptr, *pCur = nullptr;
    int2 *pBin = nullptr;
    cudaGetSymbolAddress((void**)&pPm,  g_Pmain);
    cudaGetSymbolAddress((void**)&pPb,  g_Pbias);
    cudaGetSymbolAddress((void**)&pA1,  g_agg1);
    cudaGetSymbolAddress((void**)&pA2,  g_agg2);
    cudaGetSymbolAddress((void**)&pCnt, g_cnt);
    cudaGetSymbolAddress((void**)&pOff, g_off);
    cudaGetSymbolAddress((void**)&pCur, g_cur);
    cudaGetSymbolAddress((void**)&pBin, g_bin);

    const int TB = 256;
    const int nodeGrid = (N * 8 + TB - 1) / TB;
    const int eGrid = (E + TB - 1) / TB;
    const int nGrid = (N + TB - 1) / TB;

    // CSR build (reused by both layers) — overlaps conceptually with node_prep1
    zero_cnt_kernel<<<nGrid, TB>>>(pCnt, N);
    count_kernel<<<eGrid, TB>>>(ei, pCnt, E);
    scan_kernel<<<1, 1024>>>(pCnt, pOff, pCur, N);
    fill_kernel<<<eGrid, TB>>>(ei, pCur, pBin, E);

    // Layer 1
    node_prep_kernel<16, false><<<nodeGrid, TB>>>(x, We1, be1, root1, b1, pPm, pPb, pA1, N);
    edge_csr_kernel<<<nodeGrid, TB>>>(ea, pPm, pPb, pOff, pBin, pA1, N);
    // Layer 2 (relu of agg1 inside node_prep)
    node_prep_kernel<8, true><<<nodeGrid, TB>>>(pA1, We2, be2, root2, b2, pPm, pPb, pA2, N);
    edge_csr_kernel<<<nodeGrid, TB>>>(ea, pPm, pPb, pOff, pBin, pA2, N);
    // Pool + readout
    init_out_kernel<<<(G + TB - 1) / TB, TB>>>(out, blast, G);
    pool_kernel<<<nGrid, TB>>>(pA2, batch, Wlast, out, N);
}

// round 10
// speedup vs baseline: 1.5374x; 1.5374x over previous
#include <cuda_runtime.h>
#include <cuda_fp16.h>
#include <cstdint>

// Problem constants (from reference setup_inputs)
#define MAXN 50000
#define MAXE 800000
#define NGRAPH 512
#define SCAN_B 1024

// Scratch (device globals: allocation-free).
__device__ __align__(128) __half g_Pmain[(size_t)MAXN * 64];  // [n][o*8+k]
__device__ __align__(128) __half g_Pbias[(size_t)MAXN * 8];
__device__ __align__(128) float g_agg1[(size_t)MAXN * 8];
__device__ __align__(128) float g_agg2[(size_t)MAXN * 8];
// CSR-by-dst (built once per launch, reused by both layers)
__device__ __align__(128) int    g_cnt[MAXN];
__device__ __align__(128) int    g_off[MAXN + 1];
__device__ __align__(128) int    g_cur[MAXN];
__device__ __align__(128) int    g_bsum[(MAXN + SCAN_B - 1) / SCAN_B + 1];
__device__ __align__(128) int    g_binsrc[MAXE];
__device__ __align__(128) float4 g_ea2[(size_t)MAXE * 2];   // ea permuted to bin order

// -----------------------------------------------------------------------------
// CSR build
// -----------------------------------------------------------------------------
__global__ void zero_cnt_kernel(int* __restrict__ cnt, int N)
{
    int i = blockIdx.x * blockDim.x + threadIdx.x;
    if (i < N) cnt[i] = 0;
}

__global__ void count_kernel(const int* __restrict__ ei, int* __restrict__ cnt, int E)
{
    int e = blockIdx.x * blockDim.x + threadIdx.x;
    if (e < E) atomicAdd(cnt + __ldg(ei + E + e), 1);
}

// Block-local exclusive scan (Hillis-Steele in smem) + per-block sums.
__global__ void scanA_kernel(const int* __restrict__ cnt,
                             int* __restrict__ off, int* __restrict__ bsum, int N)
{
    __shared__ int s[SCAN_B];
    int t = threadIdx.x;
    int i = blockIdx.x * SCAN_B + t;
    int v = (i < N) ? cnt[i] : 0;
    s[t] = v;
    __syncthreads();
#pragma unroll
    for (int d = 1; d < SCAN_B; d <<= 1) {
        int u = (t >= d) ? s[t - d] : 0;
        __syncthreads();
        s[t] += u;
        __syncthreads();
    }
    if (i <= N) { /* guard below */ }
    if (i < N) off[i] = s[t] - v;          // exclusive within block
    if (t == SCAN_B - 1) bsum[blockIdx.x] = s[SCAN_B - 1];
}

// Tiny serial exclusive scan of block sums (nb ~ 49).
__global__ void scanB_kernel(int* __restrict__ bsum, int nb)
{
    int acc = 0;
    for (int b = 0; b < nb; b++) {
        int v = bsum[b];
        bsum[b] = acc;
        acc += v;
    }
    bsum[nb] = acc;
}

// Add block offsets; produce cur copy and off[N].
__global__ void scanC_kernel(const int* __restrict__ cnt, int* __restrict__ off,
                             int* __restrict__ cur, const int* __restrict__ bsum, int N)
{
    int i = blockIdx.x * SCAN_B + threadIdx.x;
    if (i >= N) return;
    int v = off[i] + bsum[blockIdx.x];
    off[i] = v;
    cur[i] = v;
    if (i == N - 1) off[N] = v + cnt[i];
}

// Bin fill: scatter {src} and permuted ea rows into bin order. 2-edge ILP.
__global__ void fill_kernel(const int* __restrict__ ei, const float4* __restrict__ ea4,
                            int* __restrict__ cur, int* __restrict__ binsrc,
                            float4* __restrict__ ea2, int E)
{
    int t = blockIdx.x * blockDim.x + threadIdx.x;
    int e0 = 2 * t, e1 = 2 * t + 1;
    if (e0 >= E) return;
    bool h1 = (e1 < E);

    int dst0 = __ldg(ei + E + e0);
    int src0 = __ldg(ei + e0);
    float4 x0 = __ldg(ea4 + (size_t)e0 * 2);
    float4 y0 = __ldg(ea4 + (size_t)e0 * 2 + 1);
    int dst1 = h1 ? __ldg(ei + E + e1) : 0;
    int src1 = h1 ? __ldg(ei + e1) : 0;
    float4 x1, y1;
    if (h1) { x1 = __ldg(ea4 + (size_t)e1 * 2); y1 = __ldg(ea4 + (size_t)e1 * 2 + 1); }

    int p0 = atomicAdd(cur + dst0, 1);
    int p1 = h1 ? atomicAdd(cur + dst1, 1) : 0;

    binsrc[p0] = src0;
    ea2[(size_t)p0 * 2] = x0;
    ea2[(size_t)p0 * 2 + 1] = y0;
    if (h1) {
        binsrc[p1] = src1;
        ea2[(size_t)p1 * 2] = x1;
        ea2[(size_t)p1 * 2 + 1] = y1;
    }
}

// -----------------------------------------------------------------------------
// Node precompute: Pmain[n,o,k] = sum_i in[n,i] * We[k, i*8+o]   (fp16, transposed)
//                  Pbias[n,o]   = sum_i in[n,i] * be[i*8+o]
//                  agg[n,o] = b[o] + sum_i in[n,i] * root[i,o]   (fp32 root init)
// -----------------------------------------------------------------------------
template<int IN, bool RELU>
__global__ void node_prep_kernel(
    const float* __restrict__ xin,
    const float* __restrict__ We,    // [8, IN*8]
    const float* __restrict__ be,    // [IN*8]
    const float* __restrict__ root,  // [IN, 8]
    const float* __restrict__ bvec,  // [8]
    __half* __restrict__ Pmain,      // [N, 64]
    __half* __restrict__ Pbias,      // [N, 8]
    float* __restrict__ agg,         // [N, 8]
    int N)
{
    __shared__ float sW[8 * IN * 8];
    __shared__ float sB[IN * 8];
    __shared__ float sR[IN * 8];
    __shared__ float sb[8];
    for (int i = threadIdx.x; i < 8 * IN * 8; i += blockDim.x) sW[i] = We[i];
    for (int i = threadIdx.x; i < IN * 8; i += blockDim.x) { sB[i] = be[i]; sR[i] = root[i]; }
    if (threadIdx.x < 8) sb[threadIdx.x] = bvec[threadIdx.x];
    __syncthreads();

    int idx = blockIdx.x * blockDim.x + threadIdx.x;
    int n = idx >> 3;
    int o = idx & 7;
    if (n >= N) return;

    float xv[IN];
#pragma unroll
    for (int i = 0; i < IN; i++) {
        float v = __ldg(xin + (size_t)n * IN + i);
        xv[i] = RELU ? fmaxf(v, 0.0f) : v;
    }

    __half2 packed[4];
#pragma unroll
    for (int kk = 0; kk < 4; kk++) {
        float a0 = 0.0f, a1 = 0.0f;
#pragma unroll
        for (int i = 0; i < IN; i++) {
            a0 = fmaf(xv[i], sW[(2 * kk)     * IN * 8 + i * 8 + o], a0);
            a1 = fmaf(xv[i], sW[(2 * kk + 1) * IN * 8 + i * 8 + o], a1);
        }
        packed[kk] = __floats2half2_rn(a0, a1);
    }
    *reinterpret_cast<uint4*>(Pmain + (size_t)n * 64 + o * 8) =
        *reinterpret_cast<uint4*>(packed);

    float accb = 0.0f;
#pragma unroll
    for (int i = 0; i < IN; i++) accb = fmaf(xv[i], sB[i * 8 + o], accb);
    Pbias[(size_t)n * 8 + o] = __float2half_rn(accb);

    float accr = sb[o];
#pragma unroll
    for (int i = 0; i < IN; i++) accr = fmaf(xv[i], sR[i * 8 + o], accr);
    agg[(size_t)n * 8 + o] = accr;
}

// -----------------------------------------------------------------------------
// Edge phase, owner-computes over CSR bins (ZERO atomics):
//   8-lane group owns dst node g; iterates its bin range (coalesced binsrc +
//   ea2 reads), accumulating msg[o] = Pbias[src,o] + sum_k ea2[k]*Pmain[src,o,k].
//   One plain STG per (node, o) at the end.
// -----------------------------------------------------------------------------
__global__ void edge_csr_kernel(
    const float4* __restrict__ ea2,    // [E*2] (bin order)
    const __half* __restrict__ Pmain,  // [N, 64]
    const __half* __restrict__ Pbias,  // [N, 8]
    const int*    __restrict__ off,    // [N+1]
    const int*    __restrict__ binsrc, // [E]
    float*        __restrict__ agg,    // [N, 8] (pre-initialized with root+b)
    int N)
{
    int t = blockIdx.x * blockDim.x + threadIdx.x;
    int g = t >> 3;
    int o = t & 7;
    if (g >= N) return;

    int j   = __ldg(off + g);
    int end = __ldg(off + g + 1);
    float acc = agg[(size_t)g * 8 + o];

    for (; j + 1 < end; j += 2) {
        int s0 = __ldg(binsrc + j);
        int s1 = __ldg(binsrc + j + 1);

        float4 a00 = __ldg(ea2 + (size_t)j * 2);
        float4 a01 = __ldg(ea2 + (size_t)j * 2 + 1);
        float4 a10 = __ldg(ea2 + (size_t)j * 2 + 2);
        float4 a11 = __ldg(ea2 + (size_t)j * 2 + 3);

        uint4 raw0 = __ldg(reinterpret_cast<const uint4*>(Pmain + (size_t)s0 * 64 + o * 8));
        uint4 raw1 = __ldg(reinterpret_cast<const uint4*>(Pmain + (size_t)s1 * 64 + o * 8));
        float b0 = __half2float(__ldg(Pbias + (size_t)s0 * 8 + o));
        float b1 = __half2float(__ldg(Pbias + (size_t)s1 * 8 + o));

        __half2 ph0[4], ph1[4];
        *reinterpret_cast<uint4*>(ph0) = raw0;
        *reinterpret_cast<uint4*>(ph1) = raw1;

        float m0 = b0;
        float2 q;
        q = __half22float2(ph0[0]); m0 = fmaf(a00.x, q.x, m0); m0 = fmaf(a00.y, q.y, m0);
        q = __half22float2(ph0[1]); m0 = fmaf(a00.z, q.x, m0); m0 = fmaf(a00.w, q.y, m0);
        q = __half22float2(ph0[2]); m0 = fmaf(a01.x, q.x, m0); m0 = fmaf(a01.y, q.y, m0);
        q = __half22float2(ph0[3]); m0 = fmaf(a01.z, q.x, m0); m0 = fmaf(a01.w, q.y, m0);

        float m1 = b1;
        q = __half22float2(ph1[0]); m1 = fmaf(a10.x, q.x, m1); m1 = fmaf(a10.y, q.y, m1);
        q = __half22float2(ph1[1]); m1 = fmaf(a10.z, q.x, m1); m1 = fmaf(a10.w, q.y, m1);
        q = __half22float2(ph1[2]); m1 = fmaf(a11.x, q.x, m1); m1 = fmaf(a11.y, q.y, m1);
        q = __half22float2(ph1[3]); m1 = fmaf(a11.z, q.x, m1); m1 = fmaf(a11.w, q.y, m1);

        acc += m0 + m1;
    }
    if (j < end) {
        int s0 = __ldg(binsrc + j);
        float4 a0 = __ldg(ea2 + (size_t)j * 2);
        float4 a1 = __ldg(ea2 + (size_t)j * 2 + 1);
        uint4 raw = __ldg(reinterpret_cast<const uint4*>(Pmain + (size_t)s0 * 64 + o * 8));
        float m = __half2float(__ldg(Pbias + (size_t)s0 * 8 + o));
        __half2 ph[4];
        *reinterpret_cast<uint4*>(ph) = raw;
        float2 q;
        q = __half22float2(ph[0]); m = fmaf(a0.x, q.x, m); m = fmaf(a0.y, q.y, m);
        q = __half22float2(ph[1]); m = fmaf(a0.z, q.x, m); m = fmaf(a0.w, q.y, m);
        q = __half22float2(ph[2]); m = fmaf(a1.x, q.x, m); m = fmaf(a1.y, q.y, m);
        q = __half22float2(ph[3]); m = fmaf(a1.z, q.x, m); m = fmaf(a1.w, q.y, m);
        acc += m;
    }

    agg[(size_t)g * 8 + o] = acc;   // coalesced 32B per group, no atomics
}

// -----------------------------------------------------------------------------
// Output init: out[g] = blast[0]
// -----------------------------------------------------------------------------
__global__ void init_out_kernel(float* __restrict__ out, const float* __restrict__ blast, int G)
{
    int i = blockIdx.x * blockDim.x + threadIdx.x;
    if (i < G) out[i] = __ldg(blast);
}

// -----------------------------------------------------------------------------
// Pool + readout: out[batch[n]] += relu(agg2[n]) . Wlast
// batch is sorted -> warp-segmented reduction before atomics.
// -----------------------------------------------------------------------------
__global__ void pool_kernel(
    const float* __restrict__ agg2,
    const int*   __restrict__ batch,
    const float* __restrict__ Wlast,  // [8]
    float*       __restrict__ out,    // [G]
    int N)
{
    int n = blockIdx.x * blockDim.x + threadIdx.x;
    int lane = threadIdx.x & 31;
    bool valid = (n < N);
    float s = 0.0f;
    int g = -1;
    if (valid) {
        g = __ldg(batch + n);
#pragma unroll
        for (int o = 0; o < 8; o++) {
            float h = fmaxf(__ldg(agg2 + (size_t)n * 8 + o), 0.0f);
            s = fmaf(h, __ldg(Wlast + o), s);
        }
    }
#pragma unroll
    for (int d = 1; d < 32; d <<= 1) {
        float v = __shfl_down_sync(0xffffffffu, s, d);
        int gg   = __shfl_down_sync(0xffffffffu, g, d);
        if (lane + d < 32 && gg == g) s += v;
    }
    int gprev = __shfl_up_sync(0xffffffffu, g, 1);
    bool head = (lane == 0) || (gprev != g);
    if (valid && head) atomicAdd(out + g, s);
}

// -----------------------------------------------------------------------------
// Launch
// Inputs (metadata order): x, edge_index, edge_attr, batch,
//   We1, be1, root1, b1, We2, be2, root2, b2, Wlast, blast
// -----------------------------------------------------------------------------
extern "C" void kernel_launch(void* const* d_in, const int* in_sizes, int n_in,
                              void* d_out, int out_size)
{
    const float* x     = (const float*)d_in[0];
    const int*   ei    = (const int*)  d_in[1];
    const float* ea    = (const float*)d_in[2];
    const int*   batch = (const int*)  d_in[3];
    const float* We1   = (const float*)d_in[4];
    const float* be1   = (const float*)d_in[5];
    const float* root1 = (const float*)d_in[6];
    const float* b1    = (const float*)d_in[7];
    const float* We2   = (const float*)d_in[8];
    const float* be2   = (const float*)d_in[9];
    const float* root2 = (const float*)d_in[10];
    const float* b2    = (const float*)d_in[11];
    const float* Wlast = (const float*)d_in[12];
    const float* blast = (const float*)d_in[13];
    float* out = (float*)d_out;

    const int N = in_sizes[0] / 16;   // 50000
    const int E = in_sizes[1] / 2;    // 800000
    const int G = out_size;           // 512

    __half *pPm = nullptr, *pPb = nullptr;
    float *pA1 = nullptr, *pA2 = nullptr;
    int *pCnt = nullptr, *pOff = nullptr, *pCur = nullptr, *pBsum = nullptr, *pBinsrc = nullptr;
    float4 *pEa2 = nullptr;
    cudaGetSymbolAddress((void**)&pPm,    g_Pmain);
    cudaGetSymbolAddress((void**)&pPb,    g_Pbias);
    cudaGetSymbolAddress((void**)&pA1,    g_agg1);
    cudaGetSymbolAddress((void**)&pA2,    g_agg2);
    cudaGetSymbolAddress((void**)&pCnt,   g_cnt);
    cudaGetSymbolAddress((void**)&pOff,   g_off);
    cudaGetSymbolAddress((void**)&pCur,   g_cur);
    cudaGetSymbolAddress((void**)&pBsum,  g_bsum);
    cudaGetSymbolAddress((void**)&pBinsrc,g_binsrc);
    cudaGetSymbolAddress((void**)&pEa2,   g_ea2);

    const int TB = 256;
    const int nodeGrid = (N * 8 + TB - 1) / TB;
    const int eGrid = (E + TB - 1) / TB;
    const int nGrid = (N + TB - 1) / TB;
    const int nScanBlocks = (N + SCAN_B - 1) / SCAN_B;

    // CSR build (reused by both layers)
    zero_cnt_kernel<<<nGrid, TB>>>(pCnt, N);
    count_kernel<<<eGrid, TB>>>(ei, pCnt, E);
    scanA_kernel<<<nScanBlocks, SCAN_B>>>(pCnt, pOff, pBsum, N);
    scanB_kernel<<<1, 1>>>(pBsum, nScanBlocks);
    scanC_kernel<<<nScanBlocks, SCAN_B>>>(pCnt, pOff, pCur, pBsum, N);
    fill_kernel<<<(E / 2 + TB) / TB, TB>>>(ei, (const float4*)ea, pCur, pBinsrc, pEa2, E);

    // Layer 1
    node_prep_kernel<16, false><<<nodeGrid, TB>>>(x, We1, be1, root1, b1, pPm, pPb, pA1, N);
    edge_csr_kernel<<<nodeGrid, TB>>>(pEa2, pPm, pPb, pOff, pBinsrc, pA1, N);
    // Layer 2 (relu of agg1 inside node_prep)
    node_prep_kernel<8, true><<<nodeGrid, TB>>>(pA1, We2, be2, root2, b2, pPm, pPb, pA2, N);
    edge_csr_kernel<<<nodeGrid, TB>>>(pEa2, pPm, pPb, pOff, pBinsrc, pA2, N);
    // Pool + readout
    init_out_kernel<<<(G + TB - 1) / TB, TB>>>(out, blast, G);
    pool_kernel<<<nGrid, TB>>>(pA2, batch, Wlast, out, N);
}

// round 11
// speedup vs baseline: 2.6111x; 1.6983x over previous
#include <cuda_runtime.h>
#include <cuda_fp16.h>
#include <cstdint>

// Problem constants (from reference setup_inputs)
#define MAXN 50000
#define MAXE 800000
#define NGRAPH 512

// Scratch (device globals: allocation-free).
// g_Pmain: [N][64] half, 128B/row, 128B aligned: half[n*64 + o*8 + k] = P[n,k,o]
__device__ __align__(128) __half g_Pmain[(size_t)MAXN * 64];
__device__ __align__(128) __half g_Pbias[(size_t)MAXN * 8];
__device__ __align__(128) float  g_agg1[(size_t)MAXN * 8];
__device__ __align__(128) float  g_agg2[(size_t)MAXN * 8];
__device__ __align__(128) __half g_ea16[(size_t)MAXE * 8];   // ea rows in fp16 (16B/row)
__device__ int g_bflag[2];                                    // per-layer: any be != 0 ?

// -----------------------------------------------------------------------------
// ea -> fp16 conversion (once; reused by both layers).
// One thread per float4 (4 coeffs): read 16B, write 8B, fully coalesced.
// -----------------------------------------------------------------------------
__global__ void ea_convert_kernel(const float4* __restrict__ ea4,
                                  __half2* __restrict__ ea16, int nQuads)
{
    int i = blockIdx.x * blockDim.x + threadIdx.x;
    if (i >= nQuads) return;
    float4 v = __ldg(ea4 + i);
    ea16[2 * i]     = __floats2half2_rn(v.x, v.y);
    ea16[2 * i + 1] = __floats2half2_rn(v.z, v.w);
}

// -----------------------------------------------------------------------------
// Bias flag: bflag = 1 iff any element of be is nonzero. One block.
// -----------------------------------------------------------------------------
__global__ void biasflag_kernel(const float* __restrict__ be, int n, int* __restrict__ flag)
{
    __shared__ int any;
    if (threadIdx.x == 0) any = 0;
    __syncthreads();
    int v = 0;
    for (int i = threadIdx.x; i < n; i += blockDim.x)
        if (__ldg(be + i) != 0.0f) v = 1;
    if (__any_sync(0xffffffffu, v) && (threadIdx.x & 31) == 0) any = 1;
    __syncthreads();
    if (threadIdx.x == 0) *flag = any;
}

// -----------------------------------------------------------------------------
// Node precompute: Pmain[n,o,k] = sum_i in[n,i] * We[k, i*8+o]   (fp16, transposed)
//                  Pbias[n,o]   = sum_i in[n,i] * be[i*8+o]
//                  agg[n,o] = b[o] + sum_i in[n,i] * root[i,o]   (fp32 root init)
// One thread per (node, o). RELU applied to input when templated on.
// -----------------------------------------------------------------------------
template<int IN, bool RELU>
__global__ void node_prep_kernel(
    const float* __restrict__ xin,
    const float* __restrict__ We,    // [8, IN*8]
    const float* __restrict__ be,    // [IN*8]
    const float* __restrict__ root,  // [IN, 8]
    const float* __restrict__ bvec,  // [8]
    __half* __restrict__ Pmain,      // [N, 64]
    __half* __restrict__ Pbias,      // [N, 8]
    float* __restrict__ agg,         // [N, 8]
    int N)
{
    __shared__ float sW[8 * IN * 8];
    __shared__ float sB[IN * 8];
    __shared__ float sR[IN * 8];
    __shared__ float sb[8];
    for (int i = threadIdx.x; i < 8 * IN * 8; i += blockDim.x) sW[i] = We[i];
    for (int i = threadIdx.x; i < IN * 8; i += blockDim.x) { sB[i] = be[i]; sR[i] = root[i]; }
    if (threadIdx.x < 8) sb[threadIdx.x] = bvec[threadIdx.x];
    __syncthreads();

    int idx = blockIdx.x * blockDim.x + threadIdx.x;
    int n = idx >> 3;
    int o = idx & 7;
    if (n >= N) return;

    float xv[IN];
#pragma unroll
    for (int i = 0; i < IN; i++) {
        float v = __ldg(xin + (size_t)n * IN + i);
        xv[i] = RELU ? fmaxf(v, 0.0f) : v;
    }

    __half2 packed[4];
#pragma unroll
    for (int kk = 0; kk < 4; kk++) {
        float a0 = 0.0f, a1 = 0.0f;
#pragma unroll
        for (int i = 0; i < IN; i++) {
            a0 = fmaf(xv[i], sW[(2 * kk)     * IN * 8 + i * 8 + o], a0);
            a1 = fmaf(xv[i], sW[(2 * kk + 1) * IN * 8 + i * 8 + o], a1);
        }
        packed[kk] = __floats2half2_rn(a0, a1);
    }
    *reinterpret_cast<uint4*>(Pmain + (size_t)n * 64 + o * 8) =
        *reinterpret_cast<uint4*>(packed);

    float accb = 0.0f;
#pragma unroll
    for (int i = 0; i < IN; i++) accb = fmaf(xv[i], sB[i * 8 + o], accb);
    Pbias[(size_t)n * 8 + o] = __float2half_rn(accb);

    float accr = sb[o];
#pragma unroll
    for (int i = 0; i < IN; i++) accr = fmaf(xv[i], sR[i * 8 + o], accr);
    agg[(size_t)n * 8 + o] = accr;
}

// -----------------------------------------------------------------------------
// Edge phase: 8 threads per GROUP, 2 edges per group (independent chains).
//   thread o, edge e: msg = [bias] + sum_k ea16[e,k] * Pmain[src,o,k]
//   - ea16: 2x LDG.128 per 2 edges, group-broadcast, 1 line/warp each
//   - P gather: 1x LDG.128 per edge (one 128B line per edge)
//   - bias: loaded only if bflag (uniform branch; be==0 in this problem)
//   - scatter: full-warp scalar red.f32
// -----------------------------------------------------------------------------
__global__ void edge_kernel(
    const int*     __restrict__ ei,     // [2, E] (src row, dst row)
    const __half2* __restrict__ ea16,   // [E*4] (row = 4 half2)
    const __half*  __restrict__ Pmain,  // [N, 64]
    const __half*  __restrict__ Pbias,  // [N, 8]
    const int*     __restrict__ bflag,  // [1]
    float*         __restrict__ agg,    // [N, 8]
    int E)
{
    int t = blockIdx.x * blockDim.x + threadIdx.x;
    int g = t >> 3;
    int o = t & 7;
    int e0 = 2 * g;
    int e1 = 2 * g + 1;
    if (e0 >= E) return;
    bool has1 = (e1 < E);

    int src0 = __ldg(ei + e0);
    int src1 = has1 ? __ldg(ei + e1) : 0;
    int dst0 = __ldg(ei + E + e0);
    int dst1 = has1 ? __ldg(ei + E + e1) : 0;

    // ea rows (fp16, 16B each, adjacent): 2 broadcast LDG.128
    uint4 earaw0 = __ldg(reinterpret_cast<const uint4*>(ea16 + (size_t)e0 * 4));
    uint4 earaw1 = has1 ? __ldg(reinterpret_cast<const uint4*>(ea16 + (size_t)e1 * 4))
                        : make_uint4(0, 0, 0, 0);
    __half2 ah0[4], ah1[4];
    *reinterpret_cast<uint4*>(ah0) = earaw0;
    *reinterpret_cast<uint4*>(ah1) = earaw1;

    // P gather: one 16B load per edge per lane (one 128B line per edge)
    uint4 raw0 = __ldg(reinterpret_cast<const uint4*>(Pmain + (size_t)src0 * 64 + o * 8));
    uint4 raw1 = has1 ? __ldg(reinterpret_cast<const uint4*>(Pmain + (size_t)src1 * 64 + o * 8))
                      : make_uint4(0, 0, 0, 0);
    __half2 ph0[4], ph1[4];
    *reinterpret_cast<uint4*>(ph0) = raw0;
    *reinterpret_cast<uint4*>(ph1) = raw1;

    float m0 = 0.0f, m1 = 0.0f;
    if (__ldg(bflag)) {   // uniform branch; not taken when be == 0
        m0 = __half2float(__ldg(Pbias + (size_t)src0 * 8 + o));
        if (has1) m1 = __half2float(__ldg(Pbias + (size_t)src1 * 8 + o));
    }

#pragma unroll
    for (int kk = 0; kk < 4; kk++) {
        float2 a = __half22float2(ah0[kk]);
        float2 p = __half22float2(ph0[kk]);
        m0 = fmaf(a.x, p.x, m0);
        m0 = fmaf(a.y, p.y, m0);
    }
#pragma unroll
    for (int kk = 0; kk < 4; kk++) {
        float2 a = __half22float2(ah1[kk]);
        float2 p = __half22float2(ph1[kk]);
        m1 = fmaf(a.x, p.x, m1);
        m1 = fmaf(a.y, p.y, m1);
    }

    float* outp0 = agg + (size_t)dst0 * 8 + o;
    asm volatile("red.relaxed.gpu.global.add.f32 [%0], %1;"
                 :: "l"(outp0), "f"(m0) : "memory");
    if (has1) {
        float* outp1 = agg + (size_t)dst1 * 8 + o;
        asm volatile("red.relaxed.gpu.global.add.f32 [%0], %1;"
                     :: "l"(outp1), "f"(m1) : "memory");
    }
}

// -----------------------------------------------------------------------------
// Output init: out[g] = blast[0]
// -----------------------------------------------------------------------------
__global__ void init_out_kernel(float* __restrict__ out, const float* __restrict__ blast, int G)
{
    int i = blockIdx.x * blockDim.x + threadIdx.x;
    if (i < G) out[i] = __ldg(blast);
}

// -----------------------------------------------------------------------------
// Pool + readout: out[batch[n]] += relu(agg2[n]) . Wlast
// batch is sorted -> warp-segmented reduction before atomics.
// -----------------------------------------------------------------------------
__global__ void pool_kernel(
    const float* __restrict__ agg2,
    const int*   __restrict__ batch,
    const float* __restrict__ Wlast,  // [8]
    float*       __restrict__ out,    // [G]
    int N)
{
    int n = blockIdx.x * blockDim.x + threadIdx.x;
    int lane = threadIdx.x & 31;
    bool valid = (n < N);
    float s = 0.0f;
    int g = -1;
    if (valid) {
        g = __ldg(batch + n);
#pragma unroll
        for (int o = 0; o < 8; o++) {
            float h = fmaxf(__ldg(agg2 + (size_t)n * 8 + o), 0.0f);
            s = fmaf(h, __ldg(Wlast + o), s);
        }
    }
#pragma unroll
    for (int d = 1; d < 32; d <<= 1) {
        float v = __shfl_down_sync(0xffffffffu, s, d);
        int gg   = __shfl_down_sync(0xffffffffu, g, d);
        if (lane + d < 32 && gg == g) s += v;
    }
    int gprev = __shfl_up_sync(0xffffffffu, g, 1);
    bool head = (lane == 0) || (gprev != g);
    if (valid && head) atomicAdd(out + g, s);
}

// -----------------------------------------------------------------------------
// Launch
// Inputs (metadata order): x, edge_index, edge_attr, batch,
//   We1, be1, root1, b1, We2, be2, root2, b2, Wlast, blast
// -----------------------------------------------------------------------------
extern "C" void kernel_launch(void* const* d_in, const int* in_sizes, int n_in,
                              void* d_out, int out_size)
{
    const float* x     = (const float*)d_in[0];
    const int*   ei    = (const int*)  d_in[1];
    const float* ea    = (const float*)d_in[2];
    const int*   batch = (const int*)  d_in[3];
    const float* We1   = (const float*)d_in[4];
    const float* be1   = (const float*)d_in[5];
    const float* root1 = (const float*)d_in[6];
    const float* b1    = (const float*)d_in[7];
    const float* We2   = (const float*)d_in[8];
    const float* be2   = (const float*)d_in[9];
    const float* root2 = (const float*)d_in[10];
    const float* b2    = (const float*)d_in[11];
    const float* Wlast = (const float*)d_in[12];
    const float* blast = (const float*)d_in[13];
    float* out = (float*)d_out;

    const int N = in_sizes[0] / 16;   // 50000
    const int E = in_sizes[1] / 2;    // 800000
    const int G = out_size;           // 512

    __half *pPm = nullptr, *pPb = nullptr;
    float *pA1 = nullptr, *pA2 = nullptr;
    __half2* pEa16 = nullptr;
    int* pBf = nullptr;
    cudaGetSymbolAddress((void**)&pPm,   g_Pmain);
    cudaGetSymbolAddress((void**)&pPb,   g_Pbias);
    cudaGetSymbolAddress((void**)&pA1,   g_agg1);
    cudaGetSymbolAddress((void**)&pA2,   g_agg2);
    cudaGetSymbolAddress((void**)&pEa16, g_ea16);
    cudaGetSymbolAddress((void**)&pBf,   g_bflag);

    const int TB = 256;
    const int nodeGrid = (N * 8 + TB - 1) / TB;
    const int nGroups = (E + 1) / 2;                  // 2 edges per group
    const int edgeGrid = (nGroups * 8 + TB - 1) / TB;
    const int nQuads = E * 2;                         // float4s in ea

    // One-time prep
    ea_convert_kernel<<<(nQuads + TB - 1) / TB, TB>>>(
        (const float4*)ea, pEa16, nQuads);
    biasflag_kernel<<<1, 128>>>(be1, 16 * 8, pBf);
    biasflag_kernel<<<1, 128>>>(be2, 8 * 8, pBf + 1);

    // Layer 1
    node_prep_kernel<16, false><<<nodeGrid, TB>>>(x, We1, be1, root1, b1, pPm, pPb, pA1, N);
    edge_kernel<<<edgeGrid, TB>>>(ei, pEa16, pPm, pPb, pBf, pA1, E);
    // Layer 2 (relu of agg1 inside node_prep)
    node_prep_kernel<8, true><<<nodeGrid, TB>>>(pA1, We2, be2, root2, b2, pPm, pPb, pA2, N);
    edge_kernel<<<edgeGrid, TB>>>(ei, pEa16, pPm, pPb, pBf + 1, pA2, E);
    // Pool + readout
    init_out_kernel<<<(G + TB - 1) / TB, TB>>>(out, blast, G);
    pool_kernel<<<(N + TB - 1) / TB, TB>>>(pA2, batch, Wlast, out, N);
}

// round 13
// speedup vs baseline: 2.6314x; 1.0078x over previous
#include <cuda_runtime.h>
#include <cuda_fp16.h>
#include <cstdint>

// Problem constants (from reference setup_inputs)
#define MAXN 50000
#define MAXE 800000
#define NGRAPH 512

// Scratch (device globals: allocation-free).
// g_Pmain: [N][64] half, 128B/row, 128B aligned: half[n*64 + o*8 + k] = P[n,k,o]
__device__ __align__(128) __half g_Pmain[(size_t)MAXN * 64];
__device__ __align__(128) __half g_Pbias[(size_t)MAXN * 8];
__device__ __align__(128) float  g_agg1[(size_t)MAXN * 8];
__device__ __align__(128) float  g_agg2[(size_t)MAXN * 8];
__device__ __align__(128) __half g_ea16[(size_t)MAXE * 8];   // ea rows in fp16 (16B/row)
__device__ int g_bflag[2];                                    // per-layer: any be != 0 ?

// -----------------------------------------------------------------------------
// ea -> fp16 conversion (once; reused by both layers).
// -----------------------------------------------------------------------------
__global__ void ea_convert_kernel(const float4* __restrict__ ea4,
                                  __half2* __restrict__ ea16, int nQuads)
{
    int i = blockIdx.x * blockDim.x + threadIdx.x;
    if (i >= nQuads) return;
    float4 v = __ldg(ea4 + i);
    ea16[2 * i]     = __floats2half2_rn(v.x, v.y);
    ea16[2 * i + 1] = __floats2half2_rn(v.z, v.w);
}

// -----------------------------------------------------------------------------
// Bias flag: bflag = 1 iff any element of be is nonzero. One block.
// -----------------------------------------------------------------------------
__global__ void biasflag_kernel(const float* __restrict__ be, int n, int* __restrict__ flag)
{
    __shared__ int any;
    if (threadIdx.x == 0) any = 0;
    __syncthreads();
    int v = 0;
    for (int i = threadIdx.x; i < n; i += blockDim.x)
        if (__ldg(be + i) != 0.0f) v = 1;
    if (__any_sync(0xffffffffu, v) && (threadIdx.x & 31) == 0) any = 1;
    __syncthreads();
    if (threadIdx.x == 0) *flag = any;
}

// -----------------------------------------------------------------------------
// Node precompute (vectorized): Pmain[n,o,k] = sum_i in[n,i] * We[k, i*8+o]
//   Weights staged in shared TRANSPOSED o-major with padded stride so each
//   thread reads LDS.128 conflict-free. x read via float4.
//   Pbias computed only when bflag set. agg[n,o] = b[o] + sum_i in[n,i]*root[i,o].
// -----------------------------------------------------------------------------
template<int IN, bool RELU>
__global__ void node_prep_kernel(
    const float* __restrict__ xin,
    const float* __restrict__ We,    // [8, IN*8]
    const float* __restrict__ be,    // [IN*8]
    const float* __restrict__ root,  // [IN, 8]
    const float* __restrict__ bvec,  // [8]
    const int*   __restrict__ bflag, // [1]
    __half* __restrict__ Pmain,      // [N, 64]
    __half* __restrict__ Pbias,      // [N, 8]
    float* __restrict__ agg,         // [N, 8]
    int N)
{
    constexpr int SW_STRIDE = IN * 8 + 4;   // words; o*SW_STRIDE is 16B-aligned, banks distinct
    constexpr int R_STRIDE  = IN + 4;       // words; same properties
    __shared__ float sWp[8 * SW_STRIDE];    // [o][k*IN + i]
    __shared__ float sBp[8 * R_STRIDE];     // [o][i]
    __shared__ float sRp[8 * R_STRIDE];     // [o][i]
    __shared__ float sb[8];

    for (int idx = threadIdx.x; idx < 8 * IN * 8; idx += blockDim.x) {
        int k = idx / (IN * 8);
        int rem = idx % (IN * 8);
        int i = rem / 8;
        int o = rem % 8;
        sWp[o * SW_STRIDE + k * IN + i] = We[idx];
    }
    for (int idx = threadIdx.x; idx < IN * 8; idx += blockDim.x) {
        int i = idx / 8;
        int o = idx % 8;
        sBp[o * R_STRIDE + i] = be[idx];
        sRp[o * R_STRIDE + i] = root[idx];
    }
    if (threadIdx.x < 8) sb[threadIdx.x] = bvec[threadIdx.x];
    __syncthreads();

    int idx = blockIdx.x * blockDim.x + threadIdx.x;
    int n = idx >> 3;
    int o = idx & 7;
    if (n >= N) return;

    // x row via float4 (broadcast across the 8-lane group)
    float xv[IN];
    const float4* xq = reinterpret_cast<const float4*>(xin + (size_t)n * IN);
#pragma unroll
    for (int q = 0; q < IN / 4; q++) {
        float4 v = __ldg(xq + q);
        xv[4 * q]     = RELU ? fmaxf(v.x, 0.0f) : v.x;
        xv[4 * q + 1] = RELU ? fmaxf(v.y, 0.0f) : v.y;
        xv[4 * q + 2] = RELU ? fmaxf(v.z, 0.0f) : v.z;
        xv[4 * q + 3] = RELU ? fmaxf(v.w, 0.0f) : v.w;
    }

    const float* wbase = sWp + o * SW_STRIDE;
    float acc[8];
#pragma unroll
    for (int k = 0; k < 8; k++) {
        float a = 0.0f;
#pragma unroll
        for (int ii = 0; ii < IN / 4; ii++) {
            float4 w = *reinterpret_cast<const float4*>(wbase + k * IN + ii * 4);
            a = fmaf(xv[4 * ii],     w.x, a);
            a = fmaf(xv[4 * ii + 1], w.y, a);
            a = fmaf(xv[4 * ii + 2], w.z, a);
            a = fmaf(xv[4 * ii + 3], w.w, a);
        }
        acc[k] = a;
    }
    __half2 packed[4];
#pragma unroll
    for (int kk = 0; kk < 4; kk++)
        packed[kk] = __floats2half2_rn(acc[2 * kk], acc[2 * kk + 1]);
    *reinterpret_cast<uint4*>(Pmain + (size_t)n * 64 + o * 8) =
        *reinterpret_cast<uint4*>(packed);

    if (__ldg(bflag)) {
        const float* bbase = sBp + o * R_STRIDE;
        float accb = 0.0f;
#pragma unroll
        for (int ii = 0; ii < IN / 4; ii++) {
            float4 w = *reinterpret_cast<const float4*>(bbase + ii * 4);
            accb = fmaf(xv[4 * ii],     w.x, accb);
            accb = fmaf(xv[4 * ii + 1], w.y, accb);
            accb = fmaf(xv[4 * ii + 2], w.z, accb);
            accb = fmaf(xv[4 * ii + 3], w.w, accb);
        }
        Pbias[(size_t)n * 8 + o] = __float2half_rn(accb);
    }

    const float* rbase = sRp + o * R_STRIDE;
    float accr = sb[o];
#pragma unroll
    for (int ii = 0; ii < IN / 4; ii++) {
        float4 w = *reinterpret_cast<const float4*>(rbase + ii * 4);
        accr = fmaf(xv[4 * ii],     w.x, accr);
        accr = fmaf(xv[4 * ii + 1], w.y, accr);
        accr = fmaf(xv[4 * ii + 2], w.z, accr);
        accr = fmaf(xv[4 * ii + 3], w.w, accr);
    }
    agg[(size_t)n * 8 + o] = accr;
}

// -----------------------------------------------------------------------------
// Edge phase: 8 threads per GROUP, 2 edges per group (independent chains).
//   thread o, edge e: msg = [bias] + sum_k ea16[e,k] * Pmain[src,o,k]
// -----------------------------------------------------------------------------
__global__ void edge_kernel(
    const int*     __restrict__ ei,     // [2, E] (src row, dst row)
    const __half2* __restrict__ ea16,   // [E*4] (row = 4 half2)
    const __half*  __restrict__ Pmain,  // [N, 64]
    const __half*  __restrict__ Pbias,  // [N, 8]
    const int*     __restrict__ bflag,  // [1]
    float*         __restrict__ agg,    // [N, 8]
    int E)
{
    int t = blockIdx.x * blockDim.x + threadIdx.x;
    int g = t >> 3;
    int o = t & 7;
    int e0 = 2 * g;
    int e1 = 2 * g + 1;
    if (e0 >= E) return;
    bool has1 = (e1 < E);

    int src0 = __ldg(ei + e0);
    int src1 = has1 ? __ldg(ei + e1) : 0;
    int dst0 = __ldg(ei + E + e0);
    int dst1 = has1 ? __ldg(ei + E + e1) : 0;

    uint4 earaw0 = __ldg(reinterpret_cast<const uint4*>(ea16 + (size_t)e0 * 4));
    uint4 earaw1 = has1 ? __ldg(reinterpret_cast<const uint4*>(ea16 + (size_t)e1 * 4))
                        : make_uint4(0, 0, 0, 0);
    __half2 ah0[4], ah1[4];
    *reinterpret_cast<uint4*>(ah0) = earaw0;
    *reinterpret_cast<uint4*>(ah1) = earaw1;

    uint4 raw0 = __ldg(reinterpret_cast<const uint4*>(Pmain + (size_t)src0 * 64 + o * 8));
    uint4 raw1 = has1 ? __ldg(reinterpret_cast<const uint4*>(Pmain + (size_t)src1 * 64 + o * 8))
                      : make_uint4(0, 0, 0, 0);
    __half2 ph0[4], ph1[4];
    *reinterpret_cast<uint4*>(ph0) = raw0;
    *reinterpret_cast<uint4*>(ph1) = raw1;

    float m0 = 0.0f, m1 = 0.0f;
    if (__ldg(bflag)) {   // uniform branch; not taken when be == 0
        m0 = __half2float(__ldg(Pbias + (size_t)src0 * 8 + o));
        if (has1) m1 = __half2float(__ldg(Pbias + (size_t)src1 * 8 + o));
    }

#pragma unroll
    for (int kk = 0; kk < 4; kk++) {
        float2 a = __half22float2(ah0[kk]);
        float2 p = __half22float2(ph0[kk]);
        m0 = fmaf(a.x, p.x, m0);
        m0 = fmaf(a.y, p.y, m0);
    }
#pragma unroll
    for (int kk = 0; kk < 4; kk++) {
        float2 a = __half22float2(ah1[kk]);
        float2 p = __half22float2(ph1[kk]);
        m1 = fmaf(a.x, p.x, m1);
        m1 = fmaf(a.y, p.y, m1);
    }

    float* outp0 = agg + (size_t)dst0 * 8 + o;
    asm volatile("red.relaxed.gpu.global.add.f32 [%0], %1;"
                 :: "l"(outp0), "f"(m0) : "memory");
    if (has1) {
        float* outp1 = agg + (size_t)dst1 * 8 + o;
        asm volatile("red.relaxed.gpu.global.add.f32 [%0], %1;"
                     :: "l"(outp1), "f"(m1) : "memory");
    }
}

// -----------------------------------------------------------------------------
// Output init: out[g] = blast[0]
// -----------------------------------------------------------------------------
__global__ void init_out_kernel(float* __restrict__ out, const float* __restrict__ blast, int G)
{
    int i = blockIdx.x * blockDim.x + threadIdx.x;
    if (i < G) out[i] = __ldg(blast);
}

// -----------------------------------------------------------------------------
// Pool + readout: out[batch[n]] += relu(agg2[n]) . Wlast
// -----------------------------------------------------------------------------
__global__ void pool_kernel(
    const float* __restrict__ agg2,
    const int*   __restrict__ batch,
    const float* __restrict__ Wlast,  // [8]
    float*       __restrict__ out,    // [G]
    int N)
{
    int n = blockIdx.x * blockDim.x + threadIdx.x;
    int lane = threadIdx.x & 31;
    bool valid = (n < N);
    float s = 0.0f;
    int g = -1;
    if (valid) {
        g = __ldg(batch + n);
#pragma unroll
        for (int o = 0; o < 8; o++) {
            float h = fmaxf(__ldg(agg2 + (size_t)n * 8 + o), 0.0f);
            s = fmaf(h, __ldg(Wlast + o), s);
        }
    }
#pragma unroll
    for (int d = 1; d < 32; d <<= 1) {
        float v = __shfl_down_sync(0xffffffffu, s, d);
        int gg   = __shfl_down_sync(0xffffffffu, g, d);
        if (lane + d < 32 && gg == g) s += v;
    }
    int gprev = __shfl_up_sync(0xffffffffu, g, 1);
    bool head = (lane == 0) || (gprev != g);
    if (valid && head) atomicAdd(out + g, s);
}

// -----------------------------------------------------------------------------
// Launch
// Inputs (metadata order): x, edge_index, edge_attr, batch,
//   We1, be1, root1, b1, We2, be2, root2, b2, Wlast, blast
// -----------------------------------------------------------------------------
extern "C" void kernel_launch(void* const* d_in, const int* in_sizes, int n_in,
                              void* d_out, int out_size)
{
    const float* x     = (const float*)d_in[0];
    const int*   ei    = (const int*)  d_in[1];
    const float* ea    = (const float*)d_in[2];
    const int*   batch = (const int*)  d_in[3];
    const float* We1   = (const float*)d_in[4];
    const float* be1   = (const float*)d_in[5];
    const float* root1 = (const float*)d_in[6];
    const float* b1    = (const float*)d_in[7];
    const float* We2   = (const float*)d_in[8];
    const float* be2   = (const float*)d_in[9];
    const float* root2 = (const float*)d_in[10];
    const float* b2    = (const float*)d_in[11];
    const float* Wlast = (const float*)d_in[12];
    const float* blast = (const float*)d_in[13];
    float* out = (float*)d_out;

    const int N = in_sizes[0] / 16;   // 50000
    const int E = in_sizes[1] / 2;    // 800000
    const int G = out_size;           // 512

    __half *pPm = nullptr, *pPb = nullptr;
    float *pA1 = nullptr, *pA2 = nullptr;
    __half2* pEa16 = nullptr;
    int* pBf = nullptr;
    cudaGetSymbolAddress((void**)&pPm,   g_Pmain);
    cudaGetSymbolAddress((void**)&pPb,   g_Pbias);
    cudaGetSymbolAddress((void**)&pA1,   g_agg1);
    cudaGetSymbolAddress((void**)&pA2,   g_agg2);
    cudaGetSymbolAddress((void**)&pEa16, g_ea16);
    cudaGetSymbolAddress((void**)&pBf,   g_bflag);

    const int TB = 256;
    const int nodeGrid = (N * 8 + TB - 1) / TB;
    const int nGroups = (E + 1) / 2;                  // 2 edges per group
    const int edgeGrid = (nGroups * 8 + TB - 1) / TB;
    const int nQuads = E * 2;                         // float4s in ea

    // One-time prep
    ea_convert_kernel<<<(nQuads + TB - 1) / TB, TB>>>(
        (const float4*)ea, pEa16, nQuads);
    biasflag_kernel<<<1, 128>>>(be1, 16 * 8, pBf);
    biasflag_kernel<<<1, 128>>>(be2, 8 * 8, pBf + 1);

    // Layer 1
    node_prep_kernel<16, false><<<nodeGrid, TB>>>(x, We1, be1, root1, b1, pBf, pPm, pPb, pA1, N);
    edge_kernel<<<edgeGrid, TB>>>(ei, pEa16, pPm, pPb, pBf, pA1, E);
    // Layer 2 (relu of agg1 inside node_prep)
    node_prep_kernel<8, true><<<nodeGrid, TB>>>(pA1, We2, be2, root2, b2, pBf + 1, pPm, pPb, pA2, N);
    edge_kernel<<<edgeGrid, TB>>>(ei, pEa16, pPm, pPb, pBf + 1, pA2, E);
    // Pool + readout
    init_out_kernel<<<(G + TB - 1) / TB, TB>>>(out, blast, G);
    pool_kernel<<<(N + TB - 1) / TB, TB>>>(pA2, batch, Wlast, out, N);
}

// round 14
// speedup vs baseline: 2.8820x; 1.0952x over previous
#include <cuda_runtime.h>
#include <cuda_fp16.h>
#include <cstdint>

// Problem constants (from reference setup_inputs)
#define MAXN 50000
#define MAXE 800000
#define NGRAPH 512

// Scratch (device globals: allocation-free).
// g_Pmain: [N][64] half, 128B/row, 128B aligned: half[n*64 + o*8 + k] = P[n,k,o]
__device__ __align__(128) __half g_Pmain[(size_t)MAXN * 64];
__device__ __align__(128) __half g_Pbias[(size_t)MAXN * 8];
__device__ __align__(128) float  g_agg1[(size_t)MAXN * 8];
__device__ __align__(128) float  g_agg2[(size_t)MAXN * 8];
__device__ __align__(128) __half g_ea16[(size_t)MAXE * 8];   // ea rows in fp16 (16B/row)
__device__ int g_bflag[2];                                    // per-layer: any be != 0 ?

// -----------------------------------------------------------------------------
// ea -> fp16 conversion (once; reused by both layers).
// -----------------------------------------------------------------------------
__global__ void ea_convert_kernel(const float4* __restrict__ ea4,
                                  __half2* __restrict__ ea16, int nQuads)
{
    int i = blockIdx.x * blockDim.x + threadIdx.x;
    if (i >= nQuads) return;
    float4 v = __ldcs(ea4 + i);
    ea16[2 * i]     = __floats2half2_rn(v.x, v.y);
    ea16[2 * i + 1] = __floats2half2_rn(v.z, v.w);
}

// -----------------------------------------------------------------------------
// Bias flags (both layers in one launch): flags[l] = any(be_l != 0)
// -----------------------------------------------------------------------------
__global__ void biasflags_kernel(const float* __restrict__ be1, int n1,
                                 const float* __restrict__ be2, int n2,
                                 int* __restrict__ flags)
{
    __shared__ int any1, any2;
    if (threadIdx.x == 0) { any1 = 0; any2 = 0; }
    __syncthreads();
    int v1 = 0, v2 = 0;
    for (int i = threadIdx.x; i < n1; i += blockDim.x)
        if (__ldg(be1 + i) != 0.0f) v1 = 1;
    for (int i = threadIdx.x; i < n2; i += blockDim.x)
        if (__ldg(be2 + i) != 0.0f) v2 = 1;
    if (__any_sync(0xffffffffu, v1) && (threadIdx.x & 31) == 0) any1 = 1;
    if (__any_sync(0xffffffffu, v2) && (threadIdx.x & 31) == 0) any2 = 1;
    __syncthreads();
    if (threadIdx.x == 0) { flags[0] = any1; flags[1] = any2; }
}

// -----------------------------------------------------------------------------
// Node precompute, 2 NODES PER THREAD (halves smem-crossbar bytes per node):
//   thread (pair p, o) computes Pmain rows for n0=2p, n1=2p+1 at channel o.
//   Weights staged o-major with padded stride (conflict-free LDS.128);
//   every weight load feeds BOTH nodes' FMA chains.
//   Pbias only when bflag. agg[n,o] = b[o] + sum_i in[n,i]*root[i,o].
// -----------------------------------------------------------------------------
template<int IN, bool RELU>
__global__ void node_prep_kernel(
    const float* __restrict__ xin,
    const float* __restrict__ We,    // [8, IN*8]
    const float* __restrict__ be,    // [IN*8]
    const float* __restrict__ root,  // [IN, 8]
    const float* __restrict__ bvec,  // [8]
    const int*   __restrict__ bflag, // [1]
    __half* __restrict__ Pmain,      // [N, 64]
    __half* __restrict__ Pbias,      // [N, 8]
    float* __restrict__ agg,         // [N, 8]
    int N)
{
    constexpr int SW_STRIDE = IN * 8 + 4;   // words
    constexpr int R_STRIDE  = IN + 4;       // words
    __shared__ float sWp[8 * SW_STRIDE];    // [o][k*IN + i]
    __shared__ float sBp[8 * R_STRIDE];     // [o][i]
    __shared__ float sRp[8 * R_STRIDE];     // [o][i]
    __shared__ float sb[8];

    const int bf = __ldg(bflag);

    for (int idx = threadIdx.x; idx < 8 * IN * 8; idx += blockDim.x) {
        int k = idx / (IN * 8);
        int rem = idx % (IN * 8);
        int i = rem / 8;
        int o = rem % 8;
        sWp[o * SW_STRIDE + k * IN + i] = We[idx];
    }
    for (int idx = threadIdx.x; idx < IN * 8; idx += blockDim.x) {
        int i = idx / 8;
        int o = idx % 8;
        sRp[o * R_STRIDE + i] = root[idx];
        if (bf) sBp[o * R_STRIDE + i] = be[idx];
    }
    if (threadIdx.x < 8) sb[threadIdx.x] = bvec[threadIdx.x];
    __syncthreads();

    int idx = blockIdx.x * blockDim.x + threadIdx.x;
    int p = idx >> 3;
    int o = idx & 7;
    int n0 = 2 * p;
    int n1 = 2 * p + 1;
    if (n0 >= N) return;
    bool h1 = (n1 < N);

    const float* wbase = sWp + o * SW_STRIDE;
    const float* rbase = sRp + o * R_STRIDE;
    const float* bbase = sBp + o * R_STRIDE;

    float acc0[8], acc1[8];
#pragma unroll
    for (int k = 0; k < 8; k++) { acc0[k] = 0.0f; acc1[k] = 0.0f; }
    float accr0 = sb[o], accr1 = sb[o];
    float accb0 = 0.0f, accb1 = 0.0f;

    // i-chunked (8 inputs at a time) to bound registers; weights read ONCE
    // per chunk and applied to both nodes.
#pragma unroll
    for (int c = 0; c < IN / 8; c++) {
        float x0[8], x1[8];
        const float4* xq0 = reinterpret_cast<const float4*>(xin + (size_t)n0 * IN + c * 8);
        const float4* xq1 = reinterpret_cast<const float4*>(xin + (size_t)n1 * IN + c * 8);
#pragma unroll
        for (int q = 0; q < 2; q++) {
            float4 v0 = __ldg(xq0 + q);
            x0[4 * q]     = RELU ? fmaxf(v0.x, 0.0f) : v0.x;
            x0[4 * q + 1] = RELU ? fmaxf(v0.y, 0.0f) : v0.y;
            x0[4 * q + 2] = RELU ? fmaxf(v0.z, 0.0f) : v0.z;
            x0[4 * q + 3] = RELU ? fmaxf(v0.w, 0.0f) : v0.w;
            float4 v1 = h1 ? __ldg(xq1 + q) : make_float4(0.f, 0.f, 0.f, 0.f);
            x1[4 * q]     = RELU ? fmaxf(v1.x, 0.0f) : v1.x;
            x1[4 * q + 1] = RELU ? fmaxf(v1.y, 0.0f) : v1.y;
            x1[4 * q + 2] = RELU ? fmaxf(v1.z, 0.0f) : v1.z;
            x1[4 * q + 3] = RELU ? fmaxf(v1.w, 0.0f) : v1.w;
        }

#pragma unroll
        for (int k = 0; k < 8; k++) {
#pragma unroll
            for (int ii = 0; ii < 2; ii++) {
                float4 w = *reinterpret_cast<const float4*>(wbase + k * IN + c * 8 + ii * 4);
                acc0[k] = fmaf(x0[4 * ii],     w.x, acc0[k]);
                acc0[k] = fmaf(x0[4 * ii + 1], w.y, acc0[k]);
                acc0[k] = fmaf(x0[4 * ii + 2], w.z, acc0[k]);
                acc0[k] = fmaf(x0[4 * ii + 3], w.w, acc0[k]);
                acc1[k] = fmaf(x1[4 * ii],     w.x, acc1[k]);
                acc1[k] = fmaf(x1[4 * ii + 1], w.y, acc1[k]);
                acc1[k] = fmaf(x1[4 * ii + 2], w.z, acc1[k]);
                acc1[k] = fmaf(x1[4 * ii + 3], w.w, acc1[k]);
            }
        }
#pragma unroll
        for (int ii = 0; ii < 2; ii++) {
            float4 r = *reinterpret_cast<const float4*>(rbase + c * 8 + ii * 4);
            accr0 = fmaf(x0[4 * ii],     r.x, accr0);
            accr0 = fmaf(x0[4 * ii + 1], r.y, accr0);
            accr0 = fmaf(x0[4 * ii + 2], r.z, accr0);
            accr0 = fmaf(x0[4 * ii + 3], r.w, accr0);
            accr1 = fmaf(x1[4 * ii],     r.x, accr1);
            accr1 = fmaf(x1[4 * ii + 1], r.y, accr1);
            accr1 = fmaf(x1[4 * ii + 2], r.z, accr1);
            accr1 = fmaf(x1[4 * ii + 3], r.w, accr1);
        }
        if (bf) {
#pragma unroll
            for (int ii = 0; ii < 2; ii++) {
                float4 b = *reinterpret_cast<const float4*>(bbase + c * 8 + ii * 4);
                accb0 = fmaf(x0[4 * ii],     b.x, accb0);
                accb0 = fmaf(x0[4 * ii + 1], b.y, accb0);
                accb0 = fmaf(x0[4 * ii + 2], b.z, accb0);
                accb0 = fmaf(x0[4 * ii + 3], b.w, accb0);
                accb1 = fmaf(x1[4 * ii],     b.x, accb1);
                accb1 = fmaf(x1[4 * ii + 1], b.y, accb1);
                accb1 = fmaf(x1[4 * ii + 2], b.z, accb1);
                accb1 = fmaf(x1[4 * ii + 3], b.w, accb1);
            }
        }
    }

    __half2 packed[4];
#pragma unroll
    for (int kk = 0; kk < 4; kk++)
        packed[kk] = __floats2half2_rn(acc0[2 * kk], acc0[2 * kk + 1]);
    *reinterpret_cast<uint4*>(Pmain + (size_t)n0 * 64 + o * 8) =
        *reinterpret_cast<uint4*>(packed);
    agg[(size_t)n0 * 8 + o] = accr0;
    if (bf) Pbias[(size_t)n0 * 8 + o] = __float2half_rn(accb0);

    if (h1) {
#pragma unroll
        for (int kk = 0; kk < 4; kk++)
            packed[kk] = __floats2half2_rn(acc1[2 * kk], acc1[2 * kk + 1]);
        *reinterpret_cast<uint4*>(Pmain + (size_t)n1 * 64 + o * 8) =
            *reinterpret_cast<uint4*>(packed);
        agg[(size_t)n1 * 8 + o] = accr1;
        if (bf) Pbias[(size_t)n1 * 8 + o] = __float2half_rn(accb1);
    }
}

// -----------------------------------------------------------------------------
// Edge phase: 8 threads per GROUP, 2 edges per group (independent chains).
//   thread o, edge e: msg = [bias] + sum_k ea16[e,k] * Pmain[src,o,k]
// -----------------------------------------------------------------------------
__global__ void edge_kernel(
    const int*     __restrict__ ei,     // [2, E] (src row, dst row)
    const __half2* __restrict__ ea16,   // [E*4] (row = 4 half2)
    const __half*  __restrict__ Pmain,  // [N, 64]
    const __half*  __restrict__ Pbias,  // [N, 8]
    const int*     __restrict__ bflag,  // [1]
    float*         __restrict__ agg,    // [N, 8]
    int E)
{
    int t = blockIdx.x * blockDim.x + threadIdx.x;
    int g = t >> 3;
    int o = t & 7;
    int e0 = 2 * g;
    int e1 = 2 * g + 1;
    if (e0 >= E) return;
    bool has1 = (e1 < E);

    int src0 = __ldg(ei + e0);
    int src1 = has1 ? __ldg(ei + e1) : 0;
    int dst0 = __ldg(ei + E + e0);
    int dst1 = has1 ? __ldg(ei + E + e1) : 0;

    uint4 earaw0 = __ldg(reinterpret_cast<const uint4*>(ea16 + (size_t)e0 * 4));
    uint4 earaw1 = has1 ? __ldg(reinterpret_cast<const uint4*>(ea16 + (size_t)e1 * 4))
                        : make_uint4(0, 0, 0, 0);
    __half2 ah0[4], ah1[4];
    *reinterpret_cast<uint4*>(ah0) = earaw0;
    *reinterpret_cast<uint4*>(ah1) = earaw1;

    uint4 raw0 = __ldg(reinterpret_cast<const uint4*>(Pmain + (size_t)src0 * 64 + o * 8));
    uint4 raw1 = has1 ? __ldg(reinterpret_cast<const uint4*>(Pmain + (size_t)src1 * 64 + o * 8))
                      : make_uint4(0, 0, 0, 0);
    __half2 ph0[4], ph1[4];
    *reinterpret_cast<uint4*>(ph0) = raw0;
    *reinterpret_cast<uint4*>(ph1) = raw1;

    float m0 = 0.0f, m1 = 0.0f;
    if (__ldg(bflag)) {   // uniform branch; not taken when be == 0
        m0 = __half2float(__ldg(Pbias + (size_t)src0 * 8 + o));
        if (has1) m1 = __half2float(__ldg(Pbias + (size_t)src1 * 8 + o));
    }

#pragma unroll
    for (int kk = 0; kk < 4; kk++) {
        float2 a = __half22float2(ah0[kk]);
        float2 p = __half22float2(ph0[kk]);
        m0 = fmaf(a.x, p.x, m0);
        m0 = fmaf(a.y, p.y, m0);
    }
#pragma unroll
    for (int kk = 0; kk < 4; kk++) {
        float2 a = __half22float2(ah1[kk]);
        float2 p = __half22float2(ph1[kk]);
        m1 = fmaf(a.x, p.x, m1);
        m1 = fmaf(a.y, p.y, m1);
    }

    float* outp0 = agg + (size_t)dst0 * 8 + o;
    asm volatile("red.relaxed.gpu.global.add.f32 [%0], %1;"
                 :: "l"(outp0), "f"(m0) : "memory");
    if (has1) {
        float* outp1 = agg + (size_t)dst1 * 8 + o;
        asm volatile("red.relaxed.gpu.global.add.f32 [%0], %1;"
                     :: "l"(outp1), "f"(m1) : "memory");
    }
}

// -----------------------------------------------------------------------------
// Output init: out[g] = blast[0]
// -----------------------------------------------------------------------------
__global__ void init_out_kernel(float* __restrict__ out, const float* __restrict__ blast, int G)
{
    int i = blockIdx.x * blockDim.x + threadIdx.x;
    if (i < G) out[i] = __ldg(blast);
}

// -----------------------------------------------------------------------------
// Pool + readout: out[batch[n]] += relu(agg2[n]) . Wlast
// -----------------------------------------------------------------------------
__global__ void pool_kernel(
    const float* __restrict__ agg2,
    const int*   __restrict__ batch,
    const float* __restrict__ Wlast,  // [8]
    float*       __restrict__ out,    // [G]
    int N)
{
    int n = blockIdx.x * blockDim.x + threadIdx.x;
    int lane = threadIdx.x & 31;
    bool valid = (n < N);
    float s = 0.0f;
    int g = -1;
    if (valid) {
        g = __ldg(batch + n);
#pragma unroll
        for (int o = 0; o < 8; o++) {
            float h = fmaxf(__ldg(agg2 + (size_t)n * 8 + o), 0.0f);
            s = fmaf(h, __ldg(Wlast + o), s);
        }
    }
#pragma unroll
    for (int d = 1; d < 32; d <<= 1) {
        float v = __shfl_down_sync(0xffffffffu, s, d);
        int gg   = __shfl_down_sync(0xffffffffu, g, d);
        if (lane + d < 32 && gg == g) s += v;
    }
    int gprev = __shfl_up_sync(0xffffffffu, g, 1);
    bool head = (lane == 0) || (gprev != g);
    if (valid && head) atomicAdd(out + g, s);
}

// -----------------------------------------------------------------------------
// Launch
// Inputs (metadata order): x, edge_index, edge_attr, batch,
//   We1, be1, root1, b1, We2, be2, root2, b2, Wlast, blast
// -----------------------------------------------------------------------------
extern "C" void kernel_launch(void* const* d_in, const int* in_sizes, int n_in,
                              void* d_out, int out_size)
{
    const float* x     = (const float*)d_in[0];
    const int*   ei    = (const int*)  d_in[1];
    const float* ea    = (const float*)d_in[2];
    const int*   batch = (const int*)  d_in[3];
    const float* We1   = (const float*)d_in[4];
    const float* be1   = (const float*)d_in[5];
    const float* root1 = (const float*)d_in[6];
    const float* b1    = (const float*)d_in[7];
    const float* We2   = (const float*)d_in[8];
    const float* be2   = (const float*)d_in[9];
    const float* root2 = (const float*)d_in[10];
    const float* b2    = (const float*)d_in[11];
    const float* Wlast = (const float*)d_in[12];
    const float* blast = (const float*)d_in[13];
    float* out = (float*)d_out;

    const int N = in_sizes[0] / 16;   // 50000
    const int E = in_sizes[1] / 2;    // 800000
    const int G = out_size;           // 512

    __half *pPm = nullptr, *pPb = nullptr;
    float *pA1 = nullptr, *pA2 = nullptr;
    __half2* pEa16 = nullptr;
    int* pBf = nullptr;
    cudaGetSymbolAddress((void**)&pPm,   g_Pmain);
    cudaGetSymbolAddress((void**)&pPb,   g_Pbias);
    cudaGetSymbolAddress((void**)&pA1,   g_agg1);
    cudaGetSymbolAddress((void**)&pA2,   g_agg2);
    cudaGetSymbolAddress((void**)&pEa16, g_ea16);
    cudaGetSymbolAddress((void**)&pBf,   g_bflag);

    const int TB = 256;
    const int nPairs = (N + 1) / 2;
    const int nodeGrid = (nPairs * 8 + TB - 1) / TB;
    const int nGroups = (E + 1) / 2;                  // 2 edges per group
    const int edgeGrid = (nGroups * 8 + TB - 1) / TB;
    const int nQuads = E * 2;                         // float4s in ea

    // One-time prep
    ea_convert_kernel<<<(nQuads + TB - 1) / TB, TB>>>(
        (const float4*)ea, pEa16, nQuads);
    biasflags_kernel<<<1, 128>>>(be1, 16 * 8, be2, 8 * 8, pBf);

    // Layer 1
    node_prep_kernel<16, false><<<nodeGrid, TB>>>(x, We1, be1, root1, b1, pBf, pPm, pPb, pA1, N);
    edge_kernel<<<edgeGrid, TB>>>(ei, pEa16, pPm, pPb, pBf, pA1, E);
    // Layer 2 (relu of agg1 inside node_prep)
    node_prep_kernel<8, true><<<nodeGrid, TB>>>(pA1, We2, be2, root2, b2, pBf + 1, pPm, pPb, pA2, N);
    edge_kernel<<<edgeGrid, TB>>>(ei, pEa16, pPm, pPb, pBf + 1, pA2, E);
    // Pool + readout
    init_out_kernel<<<(G + TB - 1) / TB, TB>>>(out, blast, G);
    pool_kernel<<<(N + TB - 1) / TB, TB>>>(pA2, batch, Wlast, out, N);
}